// round 8
// baseline (speedup 1.0000x reference)
#include <cuda_runtime.h>
#include <cuda_bf16.h>
#include <math.h>
#include <stdint.h>

// ---------------- problem constants ----------------
#define NODES   20000
#define EDGES   200000
#define DIMC    256
#define HEADS   4
#define DH      64
#define INNER   256
#define EDIM    512
#define FFDIM   1024
#define OUTC    128
#define DEPTH   2

// ---------------- scratch (device globals; no allocation allowed) ----------
__device__ float g_xbuf[NODES * DIMC];
__device__ float g_xn  [NODES * DIMC];
__device__ float g_q   [NODES * DIMC];
__device__ float g_kv  [NODES * 2 * DIMC];
__device__ float g_e   [(size_t)EDGES * DIMC];
__device__ float g_sim [(size_t)EDGES * HEADS];
__device__ float g_agg [NODES * DIMC];
__device__ float g_y   [NODES * DIMC];
__device__ float g_ff  [NODES * FFDIM];
__device__ int   g_counts [NODES];
__device__ int   g_offsets[NODES + 1];
__device__ int   g_cursor [NODES];
__device__ int   g_perm   [EDGES];

// transposed split weights, [N,K] bf16, per-layer packed
#define WOFF_Q   0
#define WOFF_KV  65536
#define WOFF_E   196608
#define WOFF_O   327680
#define WOFF_F1  393216
#define WOFF_F2  655360
#define WLAYER   917504
#define WOFF_P   (2 * WLAYER)
#define WTOT     (WOFF_P + 32768)
__device__ __nv_bfloat16 g_wh[WTOT];
__device__ __nv_bfloat16 g_wl[WTOT];

__device__ __forceinline__ uint32_t smem_to_u32(const void* p) {
    uint32_t a;
    asm("{ .reg .u64 t; cvta.to.shared.u64 t, %1; cvt.u32.u64 %0, t; }" : "=r"(a) : "l"(p));
    return a;
}

// ---------------- small utility kernels ----------------
__global__ void copy_kernel(const float* __restrict__ src, float* __restrict__ dst, int n) {
    int i = blockIdx.x * blockDim.x + threadIdx.x;
    if (i < n) dst[i] = src[i];
}

__global__ void zero_counts_kernel() {
    int i = blockIdx.x * blockDim.x + threadIdx.x;
    if (i < NODES) g_counts[i] = 0;
}

__global__ void count_kernel(const int* __restrict__ dst) {
    int e = blockIdx.x * blockDim.x + threadIdx.x;
    if (e < EDGES) atomicAdd(&g_counts[dst[e]], 1);
}

// single-block exclusive scan, warp-scan based (1024 threads)
__global__ void scan_kernel() {
    __shared__ int wsum[32];
    const int CHUNK = 20;
    int tid = threadIdx.x, lane = tid & 31, wid = tid >> 5;
    int base = tid * CHUNK;
    int s = 0;
    #pragma unroll
    for (int i = 0; i < CHUNK; i++) {
        int idx = base + i;
        s += (idx < NODES) ? g_counts[idx] : 0;
    }
    int inc = s;
    #pragma unroll
    for (int o = 1; o < 32; o <<= 1) {
        int t = __shfl_up_sync(0xffffffff, inc, o);
        if (lane >= o) inc += t;
    }
    if (lane == 31) wsum[wid] = inc;
    __syncthreads();
    if (wid == 0) {
        int v = wsum[lane];
        int inc2 = v;
        #pragma unroll
        for (int o = 1; o < 32; o <<= 1) {
            int t = __shfl_up_sync(0xffffffff, inc2, o);
            if (lane >= o) inc2 += t;
        }
        wsum[lane] = inc2 - v;
    }
    __syncthreads();
    int run = wsum[wid] + (inc - s);
    #pragma unroll
    for (int i = 0; i < CHUNK; i++) {
        int idx = base + i;
        if (idx <= NODES) g_offsets[idx] = run;
        run += (idx < NODES) ? g_counts[idx] : 0;
    }
}

__global__ void cursor_init_kernel() {
    int i = blockIdx.x * blockDim.x + threadIdx.x;
    if (i < NODES) g_cursor[i] = g_offsets[i];
}

__global__ void scatter_kernel(const int* __restrict__ dst) {
    int e = blockIdx.x * blockDim.x + threadIdx.x;
    if (e < EDGES) {
        int pos = atomicAdd(&g_cursor[dst[e]], 1);
        g_perm[pos] = e;
    }
}

// ---------------- weight transpose + split: [K,N] fp32 -> [N,K] bf16 hi/lo --
__global__ void tsplit_kernel(const float* __restrict__ W, __nv_bfloat16* __restrict__ Th,
                              __nv_bfloat16* __restrict__ Tl, int K, int N) {
    __shared__ float t[32][33];
    int kb = blockIdx.y << 5, nb = blockIdx.x << 5;
    int tx = threadIdx.x, ty = threadIdx.y;  // 32 x 8
    #pragma unroll
    for (int i = 0; i < 32; i += 8)
        t[ty + i][tx] = W[(size_t)(kb + ty + i) * N + nb + tx];
    __syncthreads();
    #pragma unroll
    for (int i = 0; i < 32; i += 8) {
        int n = nb + ty + i, k = kb + tx;
        float v = t[tx][ty + i];
        __nv_bfloat16 hb = __float2bfloat16(v);
        Th[(size_t)n * K + k] = hb;
        Tl[(size_t)n * K + k] = __float2bfloat16(v - __bfloat162float(hb));
    }
}

// ---------------- LayerNorm: warp per row ----------------
__global__ void ln_kernel(const float* __restrict__ x, const float* __restrict__ g,
                          const float* __restrict__ b, float* __restrict__ out) {
    int row = blockIdx.x * (blockDim.x >> 5) + (threadIdx.x >> 5);
    if (row >= NODES) return;
    int lane = threadIdx.x & 31;
    const float* xr = x + (size_t)row * DIMC;
    float vals[8];
    float4 v0 = *(const float4*)(xr + lane * 8);
    float4 v1 = *(const float4*)(xr + lane * 8 + 4);
    vals[0]=v0.x; vals[1]=v0.y; vals[2]=v0.z; vals[3]=v0.w;
    vals[4]=v1.x; vals[5]=v1.y; vals[6]=v1.z; vals[7]=v1.w;
    float s = 0.f, ss = 0.f;
    #pragma unroll
    for (int i = 0; i < 8; i++) { s += vals[i]; ss += vals[i] * vals[i]; }
    #pragma unroll
    for (int o = 16; o > 0; o >>= 1) {
        s  += __shfl_xor_sync(0xffffffff, s,  o);
        ss += __shfl_xor_sync(0xffffffff, ss, o);
    }
    float mean = s * (1.0f / DIMC);
    float var  = ss * (1.0f / DIMC) - mean * mean;
    float rstd = rsqrtf(var + 1e-5f);
    float* orow = out + (size_t)row * DIMC;
    #pragma unroll
    for (int i = 0; i < 8; i++) {
        int c = lane * 8 + i;
        orow[c] = (vals[i] - mean) * rstd * g[c] + b[c];
    }
}

// ---------------- gated residual: warp per row ----------------
__global__ void gated_residual_kernel(const float* __restrict__ y, float* __restrict__ res,
                                      const float* __restrict__ gw) {
    int row = blockIdx.x * (blockDim.x >> 5) + (threadIdx.x >> 5);
    if (row >= NODES) return;
    int lane = threadIdx.x & 31;
    const float* yr = y   + (size_t)row * DIMC;
    float*       rr = res + (size_t)row * DIMC;
    float yv[8], rv[8];
    float z = 0.f;
    #pragma unroll
    for (int i = 0; i < 8; i++) {
        int c = lane * 8 + i;
        yv[i] = yr[c];
        rv[i] = rr[c];
        float w1 = gw[c], w2 = gw[DIMC + c], w3 = gw[2 * DIMC + c];
        z += yv[i] * (w1 + w3) + rv[i] * (w2 - w3);
    }
    #pragma unroll
    for (int o = 16; o > 0; o >>= 1) z += __shfl_xor_sync(0xffffffff, z, o);
    float gate = 1.0f / (1.0f + __expf(-z));
    #pragma unroll
    for (int i = 0; i < 8; i++) {
        int c = lane * 8 + i;
        rr[c] = yv[i] * gate + rv[i] * (1.0f - gate);
    }
}

// ====== HMMA GEMM: C[M,N] = A(fp32) @ B^T (in-kernel 3-term bf16 split) =====
// A: [M,K] fp32 row-major, split to hi/lo in-kernel.
// B_hi/B_lo: [N,K] bf16 row-major (prespilt weights).
// CTA tile 128x128, K-chunk 32, 8 warps of 64x32, mma.m16n8k16.
__device__ __forceinline__ float gelu_f(float v) {
    float c = 0.7978845608028654f * (v + 0.044715f * v * v * v);
    return 0.5f * v * (1.0f + tanhf(c));
}

#define STRB 80                       // smem bytes per 32-col bf16 row (64B + 16 pad)
#define TILEB (128 * STRB)            // 10240 B per tile
#define STAGEB (4 * TILEB)            // Ah, Al, Bh, Bl
#define GEMM_SMEM (2 * STAGEB)        // 81920 B

__device__ __forceinline__ void cp_async16(uint32_t dst, const void* src) {
    asm volatile("cp.async.cg.shared.global [%0], [%1], 16;" :: "r"(dst), "l"(src));
}
__device__ __forceinline__ void ldm_x4(uint32_t* r, uint32_t addr) {
    asm volatile("ldmatrix.sync.aligned.m8n8.x4.shared.b16 {%0,%1,%2,%3}, [%4];"
                 : "=r"(r[0]), "=r"(r[1]), "=r"(r[2]), "=r"(r[3]) : "r"(addr));
}
__device__ __forceinline__ void ldm_x2(uint32_t* r, uint32_t addr) {
    asm volatile("ldmatrix.sync.aligned.m8n8.x2.shared.b16 {%0,%1}, [%2];"
                 : "=r"(r[0]), "=r"(r[1]) : "r"(addr));
}
__device__ __forceinline__ void mma_bf16(float* d, const uint32_t* a, const uint32_t* b) {
    asm volatile("mma.sync.aligned.m16n8k16.row.col.f32.bf16.bf16.f32 "
                 "{%0,%1,%2,%3}, {%4,%5,%6,%7}, {%8,%9}, {%0,%1,%2,%3};"
                 : "+f"(d[0]), "+f"(d[1]), "+f"(d[2]), "+f"(d[3])
                 : "r"(a[0]), "r"(a[1]), "r"(a[2]), "r"(a[3]), "r"(b[0]), "r"(b[1]));
}

template<int EPI>
__global__ __launch_bounds__(256, 1) void gemm_f32a(
        const float* __restrict__ A,
        const __nv_bfloat16* __restrict__ Bh, const __nv_bfloat16* __restrict__ Bl,
        const float* __restrict__ bias, float* __restrict__ C, int M, int N, int K) {
    extern __shared__ char smem[];
    uint32_t sb = smem_to_u32(smem);
    int tid = threadIdx.x, wid = tid >> 5, lane = tid & 31;
    int bm = blockIdx.y * 128, bn = blockIdx.x * 128;
    int wm = (wid & 1) * 64, wn = (wid >> 1) * 32;

    float acc[4][4][4];
    #pragma unroll
    for (int i = 0; i < 4; i++)
        #pragma unroll
        for (int j = 0; j < 4; j++)
            #pragma unroll
            for (int k = 0; k < 4; k++) acc[i][j][k] = 0.f;

    int row_t = tid >> 1;           // 0..127
    int half  = tid & 1;            // 16-float half of 32-col row
    int nch = K >> 5;

    int gm = bm + row_t;
    const float* a_src = A + (size_t)((gm < M) ? gm : (M - 1)) * K + half * 16;
    int gn = bn + row_t;
    const char* bh_src = (const char*)(Bh + (size_t)gn * K) + half * 32;
    const char* bl_src = (const char*)(Bl + (size_t)gn * K) + half * 32;

    float4 ap[4];

    // prefetch A chunk 0 into regs; issue B chunk 0 cp.async
    #pragma unroll
    for (int q = 0; q < 4; q++) ap[q] = ((const float4*)a_src)[q];
    {
        uint32_t d0 = sb + 2 * TILEB + row_t * STRB + half * 32;
        uint32_t d1 = sb + 3 * TILEB + row_t * STRB + half * 32;
        cp_async16(d0, bh_src);      cp_async16(d0 + 16, bh_src + 16);
        cp_async16(d1, bl_src);      cp_async16(d1 + 16, bl_src + 16);
    }
    asm volatile("cp.async.commit_group;");

    int a_row = lane & 15;
    int a_col = (lane >> 4) * 16;
    int b_row = lane & 7;
    int b_col = ((lane >> 3) & 1) * 16;

    for (int c = 0; c < nch; c++) {
        int s = c & 1;
        uint32_t stg = sb + s * STAGEB;
        // convert + store A(c) regs -> smem hi/lo
        {
            uint32_t oh = stg + 0 * TILEB + row_t * STRB + half * 32;
            uint32_t ol = stg + 1 * TILEB + row_t * STRB + half * 32;
            float f[16];
            #pragma unroll
            for (int q = 0; q < 4; q++) {
                f[q*4+0] = ap[q].x; f[q*4+1] = ap[q].y; f[q*4+2] = ap[q].z; f[q*4+3] = ap[q].w;
            }
            uint32_t hp[8], lp[8];
            #pragma unroll
            for (int j = 0; j < 8; j++) {
                __nv_bfloat16 h0 = __float2bfloat16(f[2*j]);
                __nv_bfloat16 h1 = __float2bfloat16(f[2*j+1]);
                __nv_bfloat16 l0 = __float2bfloat16(f[2*j]   - __bfloat162float(h0));
                __nv_bfloat16 l1 = __float2bfloat16(f[2*j+1] - __bfloat162float(h1));
                hp[j] = (uint32_t)__bfloat16_as_ushort(h0) | ((uint32_t)__bfloat16_as_ushort(h1) << 16);
                lp[j] = (uint32_t)__bfloat16_as_ushort(l0) | ((uint32_t)__bfloat16_as_ushort(l1) << 16);
            }
            *(uint4*)(smem + (oh - sb))      = make_uint4(hp[0], hp[1], hp[2], hp[3]);
            *(uint4*)(smem + (oh - sb) + 16) = make_uint4(hp[4], hp[5], hp[6], hp[7]);
            *(uint4*)(smem + (ol - sb))      = make_uint4(lp[0], lp[1], lp[2], lp[3]);
            *(uint4*)(smem + (ol - sb) + 16) = make_uint4(lp[4], lp[5], lp[6], lp[7]);
        }
        if (c + 1 < nch) {
            // prefetch A(c+1) regs + issue B(c+1) cp.async into other stage
            const float* an = a_src + (c + 1) * 32;
            #pragma unroll
            for (int q = 0; q < 4; q++) ap[q] = ((const float4*)an)[q];
            uint32_t nst = sb + ((c + 1) & 1) * STAGEB;
            uint32_t d0 = nst + 2 * TILEB + row_t * STRB + half * 32;
            uint32_t d1 = nst + 3 * TILEB + row_t * STRB + half * 32;
            const char* pbh = bh_src + (c + 1) * 64;
            const char* pbl = bl_src + (c + 1) * 64;
            cp_async16(d0, pbh);      cp_async16(d0 + 16, pbh + 16);
            cp_async16(d1, pbl);      cp_async16(d1 + 16, pbl + 16);
            asm volatile("cp.async.commit_group;");
            asm volatile("cp.async.wait_group 1;");
        } else {
            asm volatile("cp.async.wait_group 0;");
        }
        __syncthreads();

        uint32_t sah = stg + 0 * TILEB;
        uint32_t sal = stg + 1 * TILEB;
        uint32_t sbh = stg + 2 * TILEB;
        uint32_t sbl = stg + 3 * TILEB;

        #pragma unroll
        for (int kk = 0; kk < 2; kk++) {
            uint32_t ah[4][4], al[4][4], bh[4][2], bl[4][2];
            #pragma unroll
            for (int mt = 0; mt < 4; mt++) {
                uint32_t ra = (wm + mt * 16 + a_row) * STRB + kk * 32 + a_col;
                ldm_x4(ah[mt], sah + ra);
                ldm_x4(al[mt], sal + ra);
            }
            #pragma unroll
            for (int nt = 0; nt < 4; nt++) {
                uint32_t rb = (wn + nt * 8 + b_row) * STRB + kk * 32 + b_col;
                ldm_x2(bh[nt], sbh + rb);
                ldm_x2(bl[nt], sbl + rb);
            }
            #pragma unroll
            for (int mt = 0; mt < 4; mt++)
                #pragma unroll
                for (int nt = 0; nt < 4; nt++) {
                    mma_bf16(acc[mt][nt], ah[mt], bh[nt]);
                    mma_bf16(acc[mt][nt], ah[mt], bl[nt]);
                    mma_bf16(acc[mt][nt], al[mt], bh[nt]);
                }
        }
        __syncthreads();
    }

    // epilogue
    int qm = lane >> 2, qn = 2 * (lane & 3);
    #pragma unroll
    for (int mt = 0; mt < 4; mt++) {
        #pragma unroll
        for (int nt = 0; nt < 4; nt++) {
            int m0 = bm + wm + mt * 16 + qm;
            int n0 = bn + wn + nt * 8 + qn;
            float b0 = bias[n0], b1 = bias[n0 + 1];
            #pragma unroll
            for (int hh = 0; hh < 2; hh++) {
                int m = m0 + hh * 8;
                if (m < M) {
                    float v0 = acc[mt][nt][hh * 2 + 0] + b0;
                    float v1 = acc[mt][nt][hh * 2 + 1] + b1;
                    if (EPI == 1) { v0 = gelu_f(v0); v1 = gelu_f(v1); }
                    *(float2*)(C + (size_t)m * N + n0) = make_float2(v0, v1);
                }
            }
        }
    }
}

// ---------------- attention: one block (128 thr) per destination node -------
__global__ void attn_kernel(const int* __restrict__ src) {
    __shared__ float qs[DIMC];
    __shared__ float wm[4][4], wd[4][4];
    __shared__ float fm[4], fd[4];

    int node = blockIdx.x;
    int tid = threadIdx.x;
    int warp = tid >> 5, lane = tid & 31;
    int rs  = g_offsets[node];
    int deg = g_offsets[node + 1] - rs;

    if (deg == 0) {
        g_agg[(size_t)node * DIMC + tid]       = 0.f;
        g_agg[(size_t)node * DIMC + 128 + tid] = 0.f;
        return;
    }

    qs[tid]       = g_q[(size_t)node * DIMC + tid];
    qs[tid + 128] = g_q[(size_t)node * DIMC + 128 + tid];
    __syncthreads();

    float m[4] = {-1e30f, -1e30f, -1e30f, -1e30f};
    float den[4] = {0.f, 0.f, 0.f, 0.f};
    for (int j = warp; j < deg; j += 4) {
        int eid = g_perm[rs + j];
        int s = src[eid];
        const float* kp = g_kv + (size_t)s * (2 * DIMC);
        const float* ep = g_e  + (size_t)eid * DIMC;
        float sh[4];
        #pragma unroll
        for (int h = 0; h < 4; h++) {
            int c = h * 64 + lane * 2;
            float2 kf = *(const float2*)(kp + c);
            float2 ef = *(const float2*)(ep + c);
            float2 qf = *(const float2*)(qs + c);
            sh[h] = (kf.x + ef.x) * qf.x + (kf.y + ef.y) * qf.y;
        }
        #pragma unroll
        for (int h = 0; h < 4; h++) {
            float v = sh[h];
            #pragma unroll
            for (int o = 16; o > 0; o >>= 1) v += __shfl_xor_sync(0xffffffff, v, o);
            sh[h] = v * 0.125f;
        }
        if (lane == 0) {
            *(float4*)(g_sim + (size_t)(rs + j) * 4) = make_float4(sh[0], sh[1], sh[2], sh[3]);
        }
        #pragma unroll
        for (int h = 0; h < 4; h++) {
            float mn = fmaxf(m[h], sh[h]);
            den[h] = den[h] * __expf(m[h] - mn) + __expf(sh[h] - mn);
            m[h] = mn;
        }
    }
    if (lane == 0) {
        #pragma unroll
        for (int h = 0; h < 4; h++) { wm[warp][h] = m[h]; wd[warp][h] = den[h]; }
    }
    __syncthreads();
    if (tid < 4) {
        int h = tid;
        float M_ = -1e30f;
        #pragma unroll
        for (int w = 0; w < 4; w++) M_ = fmaxf(M_, wm[w][h]);
        float D = 0.f;
        #pragma unroll
        for (int w = 0; w < 4; w++) D += wd[w][h] * __expf(wm[w][h] - M_);
        fm[h] = M_;
        fd[h] = D;
    }
    __syncthreads();

    int c0 = tid, c1 = tid + 128;
    int h0 = c0 >> 6, h1 = c1 >> 6;
    float rm0 = fm[h0], rm1 = fm[h1];
    float rd0 = 1.0f / fd[h0], rd1 = 1.0f / fd[h1];
    float acc0 = 0.f, acc1 = 0.f;
    for (int j = 0; j < deg; j++) {
        int eid = g_perm[rs + j];
        int s = src[eid];
        float p0 = __expf(g_sim[(size_t)(rs + j) * 4 + h0] - rm0) * rd0;
        float p1 = __expf(g_sim[(size_t)(rs + j) * 4 + h1] - rm1) * rd1;
        const float* vp = g_kv + (size_t)s * (2 * DIMC) + DIMC;
        const float* ep = g_e  + (size_t)eid * DIMC;
        acc0 += p0 * (vp[c0] + ep[c0]);
        acc1 += p1 * (vp[c1] + ep[c1]);
    }
    g_agg[(size_t)node * DIMC + c0] = acc0;
    g_agg[(size_t)node * DIMC + c1] = acc1;
}

// ---------------- host orchestration ----------------
static inline dim3 tc_grid(int M, int N) {
    return dim3(N / 128, (M + 127) / 128);
}

extern "C" void kernel_launch(void* const* d_in, const int* in_sizes, int n_in,
                              void* d_out, int out_size) {
    const float* x         = (const float*)d_in[0];
    const float* edge_attr = (const float*)d_in[1];
    const int*   edge_idx  = (const int*)  d_in[2];
    const float* ln1_g     = (const float*)d_in[3];
    const float* ln1_b     = (const float*)d_in[4];
    const float* Wq        = (const float*)d_in[5];
    const float* bq        = (const float*)d_in[6];
    const float* Wkv       = (const float*)d_in[7];
    const float* bkv       = (const float*)d_in[8];
    const float* We        = (const float*)d_in[9];
    const float* be        = (const float*)d_in[10];
    const float* Wo        = (const float*)d_in[11];
    const float* bo        = (const float*)d_in[12];
    const float* gate_attn = (const float*)d_in[13];
    const float* ln2_g     = (const float*)d_in[14];
    const float* ln2_b     = (const float*)d_in[15];
    const float* Wff1      = (const float*)d_in[16];
    const float* bff1      = (const float*)d_in[17];
    const float* Wff2      = (const float*)d_in[18];
    const float* bff2      = (const float*)d_in[19];
    const float* gate_ff   = (const float*)d_in[20];
    const float* Wproj     = (const float*)d_in[21];
    const float* bproj     = (const float*)d_in[22];

    const int* src_arr = edge_idx;
    const int* dst_arr = edge_idx + EDGES;

    cudaFuncSetAttribute(gemm_f32a<0>, cudaFuncAttributeMaxDynamicSharedMemorySize, GEMM_SMEM);
    cudaFuncSetAttribute(gemm_f32a<1>, cudaFuncAttributeMaxDynamicSharedMemorySize, GEMM_SMEM);

    float *p_xbuf, *p_xn, *p_q, *p_kv, *p_e, *p_agg, *p_y, *p_ff;
    __nv_bfloat16 *p_wh, *p_wl;
    cudaGetSymbolAddress((void**)&p_xbuf, g_xbuf);
    cudaGetSymbolAddress((void**)&p_xn,   g_xn);
    cudaGetSymbolAddress((void**)&p_q,    g_q);
    cudaGetSymbolAddress((void**)&p_kv,   g_kv);
    cudaGetSymbolAddress((void**)&p_e,    g_e);
    cudaGetSymbolAddress((void**)&p_agg,  g_agg);
    cudaGetSymbolAddress((void**)&p_y,    g_y);
    cudaGetSymbolAddress((void**)&p_ff,   g_ff);
    cudaGetSymbolAddress((void**)&p_wh,   g_wh);
    cudaGetSymbolAddress((void**)&p_wl,   g_wl);

    // residual init
    copy_kernel<<<(NODES * DIMC + 255) / 256, 256>>>(x, p_xbuf, NODES * DIMC);

    // CSR of incoming edges
    zero_counts_kernel<<<(NODES + 255) / 256, 256>>>();
    count_kernel<<<(EDGES + 255) / 256, 256>>>(dst_arr);
    scan_kernel<<<1, 1024>>>();
    cursor_init_kernel<<<(NODES + 255) / 256, 256>>>();
    scatter_kernel<<<(EDGES + 255) / 256, 256>>>(dst_arr);

    // weight transpose + split (once per launch; small)
    dim3 tb(32, 8);
    for (int d = 0; d < DEPTH; d++) {
        size_t wb = (size_t)d * WLAYER;
        tsplit_kernel<<<dim3(INNER/32,  DIMC/32),  tb>>>(Wq   + (size_t)d*DIMC*INNER,    p_wh + wb + WOFF_Q,  p_wl + wb + WOFF_Q,  DIMC,  INNER);
        tsplit_kernel<<<dim3(2*INNER/32,DIMC/32),  tb>>>(Wkv  + (size_t)d*DIMC*2*INNER,  p_wh + wb + WOFF_KV, p_wl + wb + WOFF_KV, DIMC,  2*INNER);
        tsplit_kernel<<<dim3(INNER/32,  EDIM/32),  tb>>>(We   + (size_t)d*EDIM*INNER,    p_wh + wb + WOFF_E,  p_wl + wb + WOFF_E,  EDIM,  INNER);
        tsplit_kernel<<<dim3(DIMC/32,   INNER/32), tb>>>(Wo   + (size_t)d*INNER*DIMC,    p_wh + wb + WOFF_O,  p_wl + wb + WOFF_O,  INNER, DIMC);
        tsplit_kernel<<<dim3(FFDIM/32,  DIMC/32),  tb>>>(Wff1 + (size_t)d*DIMC*FFDIM,    p_wh + wb + WOFF_F1, p_wl + wb + WOFF_F1, DIMC,  FFDIM);
        tsplit_kernel<<<dim3(DIMC/32,   FFDIM/32), tb>>>(Wff2 + (size_t)d*FFDIM*DIMC,    p_wh + wb + WOFF_F2, p_wl + wb + WOFF_F2, FFDIM, DIMC);
    }
    tsplit_kernel<<<dim3(OUTC/32, DIMC/32), tb>>>(Wproj, p_wh + WOFF_P, p_wl + WOFF_P, DIMC, OUTC);

    int warps_rows_blocks = (NODES + 7) / 8;

    for (int d = 0; d < DEPTH; d++) {
        size_t wb = (size_t)d * WLAYER;
        // pre-norm
        ln_kernel<<<warps_rows_blocks, 256>>>(p_xbuf, ln1_g + d * DIMC, ln1_b + d * DIMC, p_xn);
        // projections (tensor cores, fp32 A split in-kernel)
        gemm_f32a<0><<<tc_grid(NODES, INNER), 256, GEMM_SMEM>>>(
            p_xn, p_wh + wb + WOFF_Q, p_wl + wb + WOFF_Q, bq + d * INNER, p_q, NODES, INNER, DIMC);
        gemm_f32a<0><<<tc_grid(NODES, 2 * INNER), 256, GEMM_SMEM>>>(
            p_xn, p_wh + wb + WOFF_KV, p_wl + wb + WOFF_KV, bkv + d * 2 * INNER, p_kv, NODES, 2 * INNER, DIMC);
        gemm_f32a<0><<<tc_grid(EDGES, INNER), 256, GEMM_SMEM>>>(
            edge_attr, p_wh + wb + WOFF_E, p_wl + wb + WOFF_E, be + d * INNER, p_e, EDGES, INNER, EDIM);
        // sparse attention
        attn_kernel<<<NODES, 128>>>(src_arr);
        // output projection + gated residual
        gemm_f32a<0><<<tc_grid(NODES, DIMC), 256, GEMM_SMEM>>>(
            p_agg, p_wh + wb + WOFF_O, p_wl + wb + WOFF_O, bo + d * DIMC, p_y, NODES, DIMC, INNER);
        gated_residual_kernel<<<warps_rows_blocks, 256>>>(p_y, p_xbuf, gate_attn + (size_t)d * 3 * DIMC);
        // feedforward
        ln_kernel<<<warps_rows_blocks, 256>>>(p_xbuf, ln2_g + d * DIMC, ln2_b + d * DIMC, p_xn);
        gemm_f32a<1><<<tc_grid(NODES, FFDIM), 256, GEMM_SMEM>>>(
            p_xn, p_wh + wb + WOFF_F1, p_wl + wb + WOFF_F1, bff1 + d * FFDIM, p_ff, NODES, FFDIM, DIMC);
        gemm_f32a<0><<<tc_grid(NODES, DIMC), 256, GEMM_SMEM>>>(
            p_ff, p_wh + wb + WOFF_F2, p_wl + wb + WOFF_F2, bff2 + d * DIMC, p_y, NODES, DIMC, FFDIM);
        gated_residual_kernel<<<warps_rows_blocks, 256>>>(p_y, p_xbuf, gate_ff + (size_t)d * 3 * DIMC);
    }

    // final projection straight into d_out
    gemm_f32a<0><<<tc_grid(NODES, OUTC), 256, GEMM_SMEM>>>(
        p_xbuf, p_wh + WOFF_P, p_wl + WOFF_P, bproj, (float*)d_out, NODES, OUTC, DIMC);
}